// round 2
// baseline (speedup 1.0000x reference)
#include <cuda_runtime.h>
#include <cuda_bf16.h>

// Problem constants
#define C_DIM   192
#define HEADS   8
#define HD      24          // head dim = 192/8
#define HH      64
#define WW      64
#define NPIX    4096        // 64*64
#define QKV_CH  576         // 3*C

// ---------------- scratch (static device globals; no allocs) ----------------
__device__ float g_xln[C_DIM * NPIX];        // 3 MB
__device__ float g_qkv[QKV_CH * NPIX];       // 9 MB
__device__ float g_qkvdw[QKV_CH * NPIX];     // 9 MB
__device__ float g_att[C_DIM * NPIX];        // 3 MB

// ---------------- small helpers ----------------
__device__ __forceinline__ float ex2f_fast(float x) {
    float r;
    asm("ex2.approx.f32 %0, %1;" : "=f"(r) : "f"(x));
    return r;
}

// packed fp32x2 fma: (x,y) += (ax,ay)*(bx,by)
__device__ __forceinline__ void fma2(float& x, float& y, float ax, float ay, float bx, float by) {
    asm("{\n\t"
        ".reg .b64 a, b, c;\n\t"
        "mov.b64 a, {%2, %3};\n\t"
        "mov.b64 b, {%4, %5};\n\t"
        "mov.b64 c, {%0, %1};\n\t"
        "fma.rn.f32x2 c, a, b, c;\n\t"
        "mov.b64 {%0, %1}, c;\n\t"
        "}"
        : "+f"(x), "+f"(y)
        : "f"(ax), "f"(ay), "f"(bx), "f"(by));
}

// packed fp32x2 scale: (x,y) *= a
__device__ __forceinline__ void mul2(float& x, float& y, float a) {
    asm("{\n\t"
        ".reg .b64 c, s;\n\t"
        "mov.b64 c, {%0, %1};\n\t"
        "mov.b64 s, {%2, %2};\n\t"
        "mul.rn.f32x2 c, c, s;\n\t"
        "mov.b64 {%0, %1}, c;\n\t"
        "}"
        : "+f"(x), "+f"(y)
        : "f"(a));
}

// ---------------- Kernel 1: per-pixel LayerNorm over channels ----------------
__global__ void ln_kernel(const float* __restrict__ x,
                          const float* __restrict__ gamma,
                          const float* __restrict__ beta,
                          float* __restrict__ xln) {
    int p = blockIdx.x * blockDim.x + threadIdx.x;
    if (p >= NPIX) return;
    float s = 0.f, s2 = 0.f;
    #pragma unroll 8
    for (int c = 0; c < C_DIM; c++) {
        float v = x[c * NPIX + p];
        s += v;
        s2 = fmaf(v, v, s2);
    }
    const float invC = 1.0f / (float)C_DIM;
    float mean = s * invC;
    float var = s2 * invC - mean * mean;
    float inv = rsqrtf(var + 1e-5f);
    #pragma unroll 8
    for (int c = 0; c < C_DIM; c++) {
        float v = (x[c * NPIX + p] - mean) * inv;
        xln[c * NPIX + p] = fmaf(v, gamma[c], beta[c]);
    }
}

// ---------------- Kernel 2: GEMM  Y[O,N] = W[O,C] @ X[C,N] (+ optional residual) ----
// block tile 64x64, 256 threads, 4x4 micro-tile, K step 16.
__global__ __launch_bounds__(256) void gemm_kernel(
        const float* __restrict__ W, const float* __restrict__ X,
        const float* __restrict__ resid, float* __restrict__ Y,
        int O, int C, int N) {
    __shared__ __align__(16) float As[16][68];   // [k][o], padded
    __shared__ __align__(16) float Bs[16][64];   // [k][n]
    int tid = threadIdx.x;
    int tx = tid & 15;       // N dir
    int ty = tid >> 4;       // O dir
    int o0 = blockIdx.y * 64;
    int n0 = blockIdx.x * 64;

    float acc[4][4];
    #pragma unroll
    for (int i = 0; i < 4; i++)
        #pragma unroll
        for (int j = 0; j < 4; j++) acc[i][j] = 0.f;

    for (int k0 = 0; k0 < C; k0 += 16) {
        // A tile: W[o0+row][k0 + col..col+3]
        {
            int row = tid >> 2;
            int col = (tid & 3) * 4;
            float4 a = *(const float4*)&W[(o0 + row) * C + k0 + col];
            As[col + 0][row] = a.x;
            As[col + 1][row] = a.y;
            As[col + 2][row] = a.z;
            As[col + 3][row] = a.w;
        }
        // B tile: X[k0+row][n0 + col..col+3]
        {
            int row = tid >> 4;
            int col = (tid & 15) * 4;
            *(float4*)&Bs[row][col] = *(const float4*)&X[(k0 + row) * N + n0 + col];
        }
        __syncthreads();
        #pragma unroll
        for (int k = 0; k < 16; k++) {
            float4 a4 = *(const float4*)&As[k][ty * 4];
            float4 b4 = *(const float4*)&Bs[k][tx * 4];
            float a[4] = {a4.x, a4.y, a4.z, a4.w};
            float b[4] = {b4.x, b4.y, b4.z, b4.w};
            #pragma unroll
            for (int i = 0; i < 4; i++)
                #pragma unroll
                for (int j = 0; j < 4; j++)
                    acc[i][j] = fmaf(a[i], b[j], acc[i][j]);
        }
        __syncthreads();
    }

    #pragma unroll
    for (int i = 0; i < 4; i++) {
        int o = o0 + ty * 4 + i;
        int n = n0 + tx * 4;
        float4 r = make_float4(acc[i][0], acc[i][1], acc[i][2], acc[i][3]);
        if (resid) {
            float4 rv = *(const float4*)&resid[o * N + n];
            r.x += rv.x; r.y += rv.y; r.z += rv.z; r.w += rv.w;
        }
        *(float4*)&Y[o * N + n] = r;
    }
}

// ---------------- Kernel 3: depthwise 3x3 conv + bias ----------------
__global__ void dwconv_kernel(const float* __restrict__ in,
                              const float* __restrict__ w,
                              const float* __restrict__ b,
                              float* __restrict__ out) {
    int idx = blockIdx.x * blockDim.x + threadIdx.x;
    if (idx >= QKV_CH * NPIX) return;
    int xx = idx & (WW - 1);
    int yy = (idx >> 6) & (HH - 1);
    int ch = idx >> 12;
    const float* wp = &w[ch * 9];
    const float* base = &in[ch * NPIX];
    float acc = b[ch];
    #pragma unroll
    for (int dy = -1; dy <= 1; dy++) {
        int y2 = yy + dy;
        if (y2 < 0 || y2 >= HH) continue;
        #pragma unroll
        for (int dx = -1; dx <= 1; dx++) {
            int x2 = xx + dx;
            if (x2 < 0 || x2 >= WW) continue;
            acc = fmaf(base[y2 * WW + x2], wp[(dy + 1) * 3 + (dx + 1)], acc);
        }
    }
    out[idx] = acc;
}

// ---------------- Kernel 4: flash attention, 1 thread = 1 query row ----------------
// q[b,h,d,n]: channel h*24+d of qkvdw rows [0,192); k at +192; v at +384.
// attn[n,m] = sum_d q[d,n] k[d,m] * temp[h]; softmax over m; out[d,n] = sum_m p v[d,m].
#define ATT_TILE 64
__global__ __launch_bounds__(128) void attn_kernel(
        const float* __restrict__ qkv, const float* __restrict__ temp,
        float* __restrict__ out) {
    __shared__ __align__(16) float Ks[ATT_TILE][24];
    __shared__ __align__(16) float Vs[ATT_TILE][24];

    int h = blockIdx.y;
    int n = blockIdx.x * 128 + threadIdx.x;
    const float scale = temp[h] * 1.4426950408889634f;  // fold temperature * log2(e)

    float q[24];
    #pragma unroll
    for (int d = 0; d < 24; d++)
        q[d] = qkv[(h * HD + d) * NPIX + n] * scale;

    float o[24];
    #pragma unroll
    for (int d = 0; d < 24; d++) o[d] = 0.f;
    float m = -1e30f, l = 0.f;

    const float* kg = &qkv[(C_DIM + h * HD) * NPIX];
    const float* vg = &qkv[(2 * C_DIM + h * HD) * NPIX];

    for (int m0 = 0; m0 < NPIX; m0 += ATT_TILE) {
        // cooperative load, global coalesced, smem [j][d]
        #pragma unroll
        for (int e = threadIdx.x; e < ATT_TILE * 24; e += 128) {
            int d = e >> 6;
            int j = e & (ATT_TILE - 1);
            Ks[j][d] = kg[d * NPIX + m0 + j];
            Vs[j][d] = vg[d * NPIX + m0 + j];
        }
        __syncthreads();

        #pragma unroll 1
        for (int c0 = 0; c0 < ATT_TILE; c0 += 16) {
            float s[16];
            // S = q . K  (broadcast smem reads, packed fp32x2 fma)
            #pragma unroll
            for (int jj = 0; jj < 16; jj++) {
                const float4* kp = (const float4*)&Ks[c0 + jj][0];
                float ax = 0.f, ay = 0.f, bx = 0.f, by = 0.f;
                #pragma unroll
                for (int i = 0; i < 6; i += 2) {
                    float4 k0v = kp[i];
                    float4 k1v = kp[i + 1];
                    fma2(ax, ay, q[4 * i + 0], q[4 * i + 1], k0v.x, k0v.y);
                    fma2(bx, by, q[4 * i + 2], q[4 * i + 3], k0v.z, k0v.w);
                    fma2(ax, ay, q[4 * i + 4], q[4 * i + 5], k1v.x, k1v.y);
                    fma2(bx, by, q[4 * i + 6], q[4 * i + 7], k1v.z, k1v.w);
                }
                s[jj] = (ax + bx) + (ay + by);
            }
            // online softmax update
            float mx = m;
            #pragma unroll
            for (int jj = 0; jj < 16; jj++) mx = fmaxf(mx, s[jj]);
            float alpha = ex2f_fast(m - mx);
            m = mx;
            l *= alpha;
            #pragma unroll
            for (int i = 0; i < 12; i++) mul2(o[2 * i], o[2 * i + 1], alpha);
            // accumulate P @ V
            #pragma unroll
            for (int jj = 0; jj < 16; jj++) {
                float p = ex2f_fast(s[jj] - m);
                l += p;
                const float4* vp = (const float4*)&Vs[c0 + jj][0];
                #pragma unroll
                for (int i = 0; i < 6; i++) {
                    float4 vv = vp[i];
                    fma2(o[4 * i + 0], o[4 * i + 1], p, p, vv.x, vv.y);
                    fma2(o[4 * i + 2], o[4 * i + 3], p, p, vv.z, vv.w);
                }
            }
        }
        __syncthreads();
    }

    float invl = 1.0f / l;
    #pragma unroll
    for (int d = 0; d < 24; d++)
        out[(h * HD + d) * NPIX + n] = o[d] * invl;
}

// ---------------- launch ----------------
extern "C" void kernel_launch(void* const* d_in, const int* in_sizes, int n_in,
                              void* d_out, int out_size) {
    const float* x      = (const float*)d_in[0];   // [192,4096]
    const float* gamma  = (const float*)d_in[1];   // [192]
    const float* beta   = (const float*)d_in[2];   // [192]
    const float* w_qkv  = (const float*)d_in[3];   // [576,192]
    const float* w_dw   = (const float*)d_in[4];   // [576,9]
    const float* b_dw   = (const float*)d_in[5];   // [576]
    const float* w_proj = (const float*)d_in[6];   // [192,192]
    const float* temper = (const float*)d_in[7];   // [8]
    float* out = (float*)d_out;

    float *xln, *qkvb, *qkvdw, *att;
    cudaGetSymbolAddress((void**)&xln,   g_xln);
    cudaGetSymbolAddress((void**)&qkvb,  g_qkv);
    cudaGetSymbolAddress((void**)&qkvdw, g_qkvdw);
    cudaGetSymbolAddress((void**)&att,   g_att);

    // 1. LayerNorm
    ln_kernel<<<NPIX / 256, 256>>>(x, gamma, beta, xln);

    // 2. qkv = w_qkv @ xln   [576,4096]
    {
        dim3 grid(NPIX / 64, QKV_CH / 64);
        gemm_kernel<<<grid, 256>>>(w_qkv, xln, nullptr, qkvb, QKV_CH, C_DIM, NPIX);
    }

    // 3. depthwise 3x3 + bias
    dwconv_kernel<<<(QKV_CH * NPIX) / 256, 256>>>(qkvb, w_dw, b_dw, qkvdw);

    // 4. attention per head -> att [192,4096]
    {
        dim3 grid(NPIX / 128, HEADS);
        attn_kernel<<<grid, 128>>>(qkvdw, temper, att);
    }

    // 5. out = w_proj @ att + x
    {
        dim3 grid(NPIX / 64, C_DIM / 64);
        gemm_kernel<<<grid, 256>>>(w_proj, att, x, out, C_DIM, C_DIM, NPIX);
    }
}

// round 3
// speedup vs baseline: 1.0083x; 1.0083x over previous
#include <cuda_runtime.h>
#include <cuda_bf16.h>

// Problem constants
#define C_DIM   192
#define HEADS   8
#define HD      24          // head dim = 192/8
#define HH      64
#define WW      64
#define NPIX    4096        // 64*64
#define QKV_CH  576         // 3*C

// ---------------- scratch (static device globals; no allocs) ----------------
__device__ float g_xln[C_DIM * NPIX];        // 3 MB
__device__ float g_qkv[QKV_CH * NPIX];       // 9 MB
__device__ float g_qkvdw[QKV_CH * NPIX];     // 9 MB
__device__ float g_att[C_DIM * NPIX];        // 3 MB

// ---------------- small helpers ----------------
__device__ __forceinline__ float ex2f_fast(float x) {
    float r;
    asm("ex2.approx.f32 %0, %1;" : "=f"(r) : "f"(x));
    return r;
}

// packed fp32x2 fma: (x,y) += (ax,ay)*(bx,by)
__device__ __forceinline__ void fma2(float& x, float& y, float ax, float ay, float bx, float by) {
    asm("{\n\t"
        ".reg .b64 a, b, c;\n\t"
        "mov.b64 a, {%2, %3};\n\t"
        "mov.b64 b, {%4, %5};\n\t"
        "mov.b64 c, {%0, %1};\n\t"
        "fma.rn.f32x2 c, a, b, c;\n\t"
        "mov.b64 {%0, %1}, c;\n\t"
        "}"
        : "+f"(x), "+f"(y)
        : "f"(ax), "f"(ay), "f"(bx), "f"(by));
}

// packed fp32x2 scale: (x,y) *= a
__device__ __forceinline__ void mul2(float& x, float& y, float a) {
    asm("{\n\t"
        ".reg .b64 c, s;\n\t"
        "mov.b64 c, {%0, %1};\n\t"
        "mov.b64 s, {%2, %2};\n\t"
        "mul.rn.f32x2 c, c, s;\n\t"
        "mov.b64 {%0, %1}, c;\n\t"
        "}"
        : "+f"(x), "+f"(y)
        : "f"(a));
}

// ---------------- Kernel 1: per-pixel LayerNorm over channels ----------------
__global__ void ln_kernel(const float* __restrict__ x,
                          const float* __restrict__ gamma,
                          const float* __restrict__ beta,
                          float* __restrict__ xln) {
    int p = blockIdx.x * blockDim.x + threadIdx.x;
    if (p >= NPIX) return;
    float s = 0.f, s2 = 0.f;
    #pragma unroll 8
    for (int c = 0; c < C_DIM; c++) {
        float v = x[c * NPIX + p];
        s += v;
        s2 = fmaf(v, v, s2);
    }
    const float invC = 1.0f / (float)C_DIM;
    float mean = s * invC;
    float var = s2 * invC - mean * mean;
    float inv = rsqrtf(var + 1e-5f);
    #pragma unroll 8
    for (int c = 0; c < C_DIM; c++) {
        float v = (x[c * NPIX + p] - mean) * inv;
        xln[c * NPIX + p] = fmaf(v, gamma[c], beta[c]);
    }
}

// ---------------- Kernel 2: GEMM  Y[O,N] = W[O,C] @ X[C,N] (+ optional residual) ----
// block tile 64x64, 256 threads, 4x4 micro-tile, K step 16.
__global__ __launch_bounds__(256) void gemm_kernel(
        const float* __restrict__ W, const float* __restrict__ X,
        const float* __restrict__ resid, float* __restrict__ Y,
        int O, int C, int N) {
    __shared__ __align__(16) float As[16][68];   // [k][o], padded
    __shared__ __align__(16) float Bs[16][64];   // [k][n]
    int tid = threadIdx.x;
    int tx = tid & 15;       // N dir
    int ty = tid >> 4;       // O dir
    int o0 = blockIdx.y * 64;
    int n0 = blockIdx.x * 64;

    float acc[4][4];
    #pragma unroll
    for (int i = 0; i < 4; i++)
        #pragma unroll
        for (int j = 0; j < 4; j++) acc[i][j] = 0.f;

    for (int k0 = 0; k0 < C; k0 += 16) {
        // A tile: W[o0+row][k0 + col..col+3]
        {
            int row = tid >> 2;
            int col = (tid & 3) * 4;
            float4 a = *(const float4*)&W[(o0 + row) * C + k0 + col];
            As[col + 0][row] = a.x;
            As[col + 1][row] = a.y;
            As[col + 2][row] = a.z;
            As[col + 3][row] = a.w;
        }
        // B tile: X[k0+row][n0 + col..col+3]
        {
            int row = tid >> 4;
            int col = (tid & 15) * 4;
            *(float4*)&Bs[row][col] = *(const float4*)&X[(k0 + row) * N + n0 + col];
        }
        __syncthreads();
        #pragma unroll
        for (int k = 0; k < 16; k++) {
            float4 a4 = *(const float4*)&As[k][ty * 4];
            float4 b4 = *(const float4*)&Bs[k][tx * 4];
            float a[4] = {a4.x, a4.y, a4.z, a4.w};
            float b[4] = {b4.x, b4.y, b4.z, b4.w};
            #pragma unroll
            for (int i = 0; i < 4; i++)
                #pragma unroll
                for (int j = 0; j < 4; j++)
                    acc[i][j] = fmaf(a[i], b[j], acc[i][j]);
        }
        __syncthreads();
    }

    #pragma unroll
    for (int i = 0; i < 4; i++) {
        int o = o0 + ty * 4 + i;
        int n = n0 + tx * 4;
        float4 r = make_float4(acc[i][0], acc[i][1], acc[i][2], acc[i][3]);
        if (resid) {
            float4 rv = *(const float4*)&resid[o * N + n];
            r.x += rv.x; r.y += rv.y; r.z += rv.z; r.w += rv.w;
        }
        *(float4*)&Y[o * N + n] = r;
    }
}

// ---------------- Kernel 3: depthwise 3x3 conv + bias ----------------
__global__ void dwconv_kernel(const float* __restrict__ in,
                              const float* __restrict__ w,
                              const float* __restrict__ b,
                              float* __restrict__ out) {
    int idx = blockIdx.x * blockDim.x + threadIdx.x;
    if (idx >= QKV_CH * NPIX) return;
    int xx = idx & (WW - 1);
    int yy = (idx >> 6) & (HH - 1);
    int ch = idx >> 12;
    const float* wp = &w[ch * 9];
    const float* base = &in[ch * NPIX];
    float acc = b[ch];
    #pragma unroll
    for (int dy = -1; dy <= 1; dy++) {
        int y2 = yy + dy;
        if (y2 < 0 || y2 >= HH) continue;
        #pragma unroll
        for (int dx = -1; dx <= 1; dx++) {
            int x2 = xx + dx;
            if (x2 < 0 || x2 >= WW) continue;
            acc = fmaf(base[y2 * WW + x2], wp[(dy + 1) * 3 + (dx + 1)], acc);
        }
    }
    out[idx] = acc;
}

// ---------------- Kernel 4: flash attention, 1 thread = 1 query row ----------------
// q[b,h,d,n]: channel h*24+d of qkvdw rows [0,192); k at +192; v at +384.
// attn[n,m] = sum_d q[d,n] k[d,m] * temp[h]; softmax over m; out[d,n] = sum_m p v[d,m].
#define ATT_TILE 64
__global__ __launch_bounds__(128) void attn_kernel(
        const float* __restrict__ qkv, const float* __restrict__ temp,
        float* __restrict__ out) {
    __shared__ __align__(16) float Ks[ATT_TILE][24];
    __shared__ __align__(16) float Vs[ATT_TILE][24];

    int h = blockIdx.y;
    int n = blockIdx.x * 128 + threadIdx.x;
    const float scale = temp[h] * 1.4426950408889634f;  // fold temperature * log2(e)

    float q[24];
    #pragma unroll
    for (int d = 0; d < 24; d++)
        q[d] = qkv[(h * HD + d) * NPIX + n] * scale;

    float o[24];
    #pragma unroll
    for (int d = 0; d < 24; d++) o[d] = 0.f;
    float m = -1e30f, l = 0.f;

    const float* kg = &qkv[(C_DIM + h * HD) * NPIX];
    const float* vg = &qkv[(2 * C_DIM + h * HD) * NPIX];

    for (int m0 = 0; m0 < NPIX; m0 += ATT_TILE) {
        // cooperative load, global coalesced, smem [j][d]
        #pragma unroll
        for (int e = threadIdx.x; e < ATT_TILE * 24; e += 128) {
            int d = e >> 6;
            int j = e & (ATT_TILE - 1);
            Ks[j][d] = kg[d * NPIX + m0 + j];
            Vs[j][d] = vg[d * NPIX + m0 + j];
        }
        __syncthreads();

        #pragma unroll 1
        for (int c0 = 0; c0 < ATT_TILE; c0 += 16) {
            float s[16];
            // S = q . K  (broadcast smem reads, packed fp32x2 fma)
            #pragma unroll
            for (int jj = 0; jj < 16; jj++) {
                const float4* kp = (const float4*)&Ks[c0 + jj][0];
                float ax = 0.f, ay = 0.f, bx = 0.f, by = 0.f;
                #pragma unroll
                for (int i = 0; i < 6; i += 2) {
                    float4 k0v = kp[i];
                    float4 k1v = kp[i + 1];
                    fma2(ax, ay, q[4 * i + 0], q[4 * i + 1], k0v.x, k0v.y);
                    fma2(bx, by, q[4 * i + 2], q[4 * i + 3], k0v.z, k0v.w);
                    fma2(ax, ay, q[4 * i + 4], q[4 * i + 5], k1v.x, k1v.y);
                    fma2(bx, by, q[4 * i + 6], q[4 * i + 7], k1v.z, k1v.w);
                }
                s[jj] = (ax + bx) + (ay + by);
            }
            // online softmax update
            float mx = m;
            #pragma unroll
            for (int jj = 0; jj < 16; jj++) mx = fmaxf(mx, s[jj]);
            float alpha = ex2f_fast(m - mx);
            m = mx;
            l *= alpha;
            #pragma unroll
            for (int i = 0; i < 12; i++) mul2(o[2 * i], o[2 * i + 1], alpha);
            // accumulate P @ V
            #pragma unroll
            for (int jj = 0; jj < 16; jj++) {
                float p = ex2f_fast(s[jj] - m);
                l += p;
                const float4* vp = (const float4*)&Vs[c0 + jj][0];
                #pragma unroll
                for (int i = 0; i < 6; i++) {
                    float4 vv = vp[i];
                    fma2(o[4 * i + 0], o[4 * i + 1], p, p, vv.x, vv.y);
                    fma2(o[4 * i + 2], o[4 * i + 3], p, p, vv.z, vv.w);
                }
            }
        }
        __syncthreads();
    }

    float invl = 1.0f / l;
    #pragma unroll
    for (int d = 0; d < 24; d++)
        out[(h * HD + d) * NPIX + n] = o[d] * invl;
}

// ---------------- launch ----------------
extern "C" void kernel_launch(void* const* d_in, const int* in_sizes, int n_in,
                              void* d_out, int out_size) {
    const float* x      = (const float*)d_in[0];   // [192,4096]
    const float* gamma  = (const float*)d_in[1];   // [192]
    const float* beta   = (const float*)d_in[2];   // [192]
    const float* w_qkv  = (const float*)d_in[3];   // [576,192]
    const float* w_dw   = (const float*)d_in[4];   // [576,9]
    const float* b_dw   = (const float*)d_in[5];   // [576]
    const float* w_proj = (const float*)d_in[6];   // [192,192]
    const float* temper = (const float*)d_in[7];   // [8]
    float* out = (float*)d_out;

    float *xln, *qkvb, *qkvdw, *att;
    cudaGetSymbolAddress((void**)&xln,   g_xln);
    cudaGetSymbolAddress((void**)&qkvb,  g_qkv);
    cudaGetSymbolAddress((void**)&qkvdw, g_qkvdw);
    cudaGetSymbolAddress((void**)&att,   g_att);

    // 1. LayerNorm
    ln_kernel<<<NPIX / 256, 256>>>(x, gamma, beta, xln);

    // 2. qkv = w_qkv @ xln   [576,4096]
    {
        dim3 grid(NPIX / 64, QKV_CH / 64);
        gemm_kernel<<<grid, 256>>>(w_qkv, xln, nullptr, qkvb, QKV_CH, C_DIM, NPIX);
    }

    // 3. depthwise 3x3 + bias
    dwconv_kernel<<<(QKV_CH * NPIX) / 256, 256>>>(qkvb, w_dw, b_dw, qkvdw);

    // 4. attention per head -> att [192,4096]
    {
        dim3 grid(NPIX / 128, HEADS);
        attn_kernel<<<grid, 128>>>(qkvdw, temper, att);
    }

    // 5. out = w_proj @ att + x
    {
        dim3 grid(NPIX / 64, C_DIM / 64);
        gemm_kernel<<<grid, 256>>>(w_proj, att, x, out, C_DIM, C_DIM, NPIX);
    }
}

// round 4
// speedup vs baseline: 1.4615x; 1.4496x over previous
#include <cuda_runtime.h>
#include <cuda_bf16.h>

// Problem constants
#define C_DIM   192
#define HEADS   8
#define HD      24          // head dim = 192/8
#define HH      64
#define WW      64
#define NPIX    4096        // 64*64
#define QKV_CH  576         // 3*C
#define SPLITS  8
#define MCHUNK  (NPIX / SPLITS)   // 512

// ---------------- scratch (static device globals; no allocs) ----------------
__device__ float g_xln[C_DIM * NPIX];                 // 3 MB
__device__ float g_qkv[QKV_CH * NPIX];                // 9 MB
__device__ float g_qkvdw[QKV_CH * NPIX];              // 9 MB
__device__ float g_att[C_DIM * NPIX];                 // 3 MB
__device__ float g_po[SPLITS * HEADS * HD * NPIX];    // 25 MB partial outputs
__device__ float g_pm[SPLITS * HEADS * NPIX];         // partial max (log2 domain)
__device__ float g_pl[SPLITS * HEADS * NPIX];         // partial sum

// ---------------- small helpers ----------------
__device__ __forceinline__ float ex2f_fast(float x) {
    float r;
    asm("ex2.approx.f32 %0, %1;" : "=f"(r) : "f"(x));
    return r;
}

// packed fp32x2 fma: (x,y) += (ax,ay)*(bx,by)
__device__ __forceinline__ void fma2(float& x, float& y, float ax, float ay, float bx, float by) {
    asm("{\n\t"
        ".reg .b64 a, b, c;\n\t"
        "mov.b64 a, {%2, %3};\n\t"
        "mov.b64 b, {%4, %5};\n\t"
        "mov.b64 c, {%0, %1};\n\t"
        "fma.rn.f32x2 c, a, b, c;\n\t"
        "mov.b64 {%0, %1}, c;\n\t"
        "}"
        : "+f"(x), "+f"(y)
        : "f"(ax), "f"(ay), "f"(bx), "f"(by));
}

// packed fp32x2 scale: (x,y) *= a
__device__ __forceinline__ void mul2(float& x, float& y, float a) {
    asm("{\n\t"
        ".reg .b64 c, s;\n\t"
        "mov.b64 c, {%0, %1};\n\t"
        "mov.b64 s, {%2, %2};\n\t"
        "mul.rn.f32x2 c, c, s;\n\t"
        "mov.b64 {%0, %1}, c;\n\t"
        "}"
        : "+f"(x), "+f"(y)
        : "f"(a));
}

// ---------------- Kernel 1: per-pixel LayerNorm over channels ----------------
__global__ void ln_kernel(const float* __restrict__ x,
                          const float* __restrict__ gamma,
                          const float* __restrict__ beta,
                          float* __restrict__ xln) {
    int p = blockIdx.x * blockDim.x + threadIdx.x;
    if (p >= NPIX) return;
    float s = 0.f, s2 = 0.f;
    #pragma unroll 8
    for (int c = 0; c < C_DIM; c++) {
        float v = x[c * NPIX + p];
        s += v;
        s2 = fmaf(v, v, s2);
    }
    const float invC = 1.0f / (float)C_DIM;
    float mean = s * invC;
    float var = s2 * invC - mean * mean;
    float inv = rsqrtf(var + 1e-5f);
    #pragma unroll 8
    for (int c = 0; c < C_DIM; c++) {
        float v = (x[c * NPIX + p] - mean) * inv;
        xln[c * NPIX + p] = fmaf(v, gamma[c], beta[c]);
    }
}

// ---------------- Kernel 2: GEMM  Y[O,N] = W[O,C] @ X[C,N] (+ optional residual) ----
__global__ __launch_bounds__(256) void gemm_kernel(
        const float* __restrict__ W, const float* __restrict__ X,
        const float* __restrict__ resid, float* __restrict__ Y,
        int O, int C, int N) {
    __shared__ __align__(16) float As[16][68];   // [k][o], padded
    __shared__ __align__(16) float Bs[16][64];   // [k][n]
    int tid = threadIdx.x;
    int tx = tid & 15;       // N dir
    int ty = tid >> 4;       // O dir
    int o0 = blockIdx.y * 64;
    int n0 = blockIdx.x * 64;

    float acc[4][4];
    #pragma unroll
    for (int i = 0; i < 4; i++)
        #pragma unroll
        for (int j = 0; j < 4; j++) acc[i][j] = 0.f;

    for (int k0 = 0; k0 < C; k0 += 16) {
        {
            int row = tid >> 2;
            int col = (tid & 3) * 4;
            float4 a = *(const float4*)&W[(o0 + row) * C + k0 + col];
            As[col + 0][row] = a.x;
            As[col + 1][row] = a.y;
            As[col + 2][row] = a.z;
            As[col + 3][row] = a.w;
        }
        {
            int row = tid >> 4;
            int col = (tid & 15) * 4;
            *(float4*)&Bs[row][col] = *(const float4*)&X[(k0 + row) * N + n0 + col];
        }
        __syncthreads();
        #pragma unroll
        for (int k = 0; k < 16; k++) {
            float4 a4 = *(const float4*)&As[k][ty * 4];
            float4 b4 = *(const float4*)&Bs[k][tx * 4];
            float a[4] = {a4.x, a4.y, a4.z, a4.w};
            float b[4] = {b4.x, b4.y, b4.z, b4.w};
            #pragma unroll
            for (int i = 0; i < 4; i++)
                #pragma unroll
                for (int j = 0; j < 4; j++)
                    acc[i][j] = fmaf(a[i], b[j], acc[i][j]);
        }
        __syncthreads();
    }

    #pragma unroll
    for (int i = 0; i < 4; i++) {
        int o = o0 + ty * 4 + i;
        int n = n0 + tx * 4;
        float4 r = make_float4(acc[i][0], acc[i][1], acc[i][2], acc[i][3]);
        if (resid) {
            float4 rv = *(const float4*)&resid[o * N + n];
            r.x += rv.x; r.y += rv.y; r.z += rv.z; r.w += rv.w;
        }
        *(float4*)&Y[o * N + n] = r;
    }
}

// ---------------- Kernel 3: depthwise 3x3 conv + bias ----------------
__global__ void dwconv_kernel(const float* __restrict__ in,
                              const float* __restrict__ w,
                              const float* __restrict__ b,
                              float* __restrict__ out) {
    int idx = blockIdx.x * blockDim.x + threadIdx.x;
    if (idx >= QKV_CH * NPIX) return;
    int xx = idx & (WW - 1);
    int yy = (idx >> 6) & (HH - 1);
    int ch = idx >> 12;
    const float* wp = &w[ch * 9];
    const float* base = &in[ch * NPIX];
    float acc = b[ch];
    #pragma unroll
    for (int dy = -1; dy <= 1; dy++) {
        int y2 = yy + dy;
        if (y2 < 0 || y2 >= HH) continue;
        #pragma unroll
        for (int dx = -1; dx <= 1; dx++) {
            int x2 = xx + dx;
            if (x2 < 0 || x2 >= WW) continue;
            acc = fmaf(base[y2 * WW + x2], wp[(dy + 1) * 3 + (dx + 1)], acc);
        }
    }
    out[idx] = acc;
}

// ---------------- Kernel 4: flash attention partials (split-KV) ----------------
// Each block: 256 queries (1/thread) x one KV chunk of MCHUNK=512 positions.
#define ATT_TILE 64
__global__ __launch_bounds__(256) void attn_part_kernel(
        const float* __restrict__ qkv, const float* __restrict__ temp,
        float* __restrict__ po, float* __restrict__ pm, float* __restrict__ pl) {
    __shared__ __align__(16) float Ks[ATT_TILE][24];
    __shared__ __align__(16) float Vs[ATT_TILE][24];

    int h = blockIdx.y;
    int sp = blockIdx.z;
    int n = blockIdx.x * 256 + threadIdx.x;
    const float scale = temp[h] * 1.4426950408889634f;  // temperature * log2(e)

    float q[24];
    #pragma unroll
    for (int d = 0; d < 24; d++)
        q[d] = qkv[(h * HD + d) * NPIX + n] * scale;

    float o[24];
    #pragma unroll
    for (int d = 0; d < 24; d++) o[d] = 0.f;
    float m = -1e30f, l = 0.f;

    const float* kg = &qkv[(C_DIM + h * HD) * NPIX];
    const float* vg = &qkv[(2 * C_DIM + h * HD) * NPIX];

    const int mbeg = sp * MCHUNK;
    const int mend = mbeg + MCHUNK;

    for (int m0 = mbeg; m0 < mend; m0 += ATT_TILE) {
        // cooperative load, global coalesced, smem [j][d]
        #pragma unroll
        for (int e = threadIdx.x; e < ATT_TILE * 24; e += 256) {
            int d = e >> 6;
            int j = e & (ATT_TILE - 1);
            Ks[j][d] = kg[d * NPIX + m0 + j];
            Vs[j][d] = vg[d * NPIX + m0 + j];
        }
        __syncthreads();

        #pragma unroll 1
        for (int c0 = 0; c0 < ATT_TILE; c0 += 16) {
            float s[16];
            // S = q . K  (broadcast smem reads, packed fp32x2 fma)
            #pragma unroll
            for (int jj = 0; jj < 16; jj++) {
                const float4* kp = (const float4*)&Ks[c0 + jj][0];
                float ax = 0.f, ay = 0.f, bx = 0.f, by = 0.f;
                #pragma unroll
                for (int i = 0; i < 6; i += 2) {
                    float4 k0v = kp[i];
                    float4 k1v = kp[i + 1];
                    fma2(ax, ay, q[4 * i + 0], q[4 * i + 1], k0v.x, k0v.y);
                    fma2(bx, by, q[4 * i + 2], q[4 * i + 3], k0v.z, k0v.w);
                    fma2(ax, ay, q[4 * i + 4], q[4 * i + 5], k1v.x, k1v.y);
                    fma2(bx, by, q[4 * i + 6], q[4 * i + 7], k1v.z, k1v.w);
                }
                s[jj] = (ax + bx) + (ay + by);
            }
            // online softmax update
            float mx = m;
            #pragma unroll
            for (int jj = 0; jj < 16; jj++) mx = fmaxf(mx, s[jj]);
            float alpha = ex2f_fast(m - mx);
            m = mx;
            l *= alpha;
            #pragma unroll
            for (int i = 0; i < 12; i++) mul2(o[2 * i], o[2 * i + 1], alpha);
            // accumulate P @ V
            #pragma unroll
            for (int jj = 0; jj < 16; jj++) {
                float p = ex2f_fast(s[jj] - m);
                l += p;
                const float4* vp = (const float4*)&Vs[c0 + jj][0];
                #pragma unroll
                for (int i = 0; i < 6; i++) {
                    float4 vv = vp[i];
                    fma2(o[4 * i + 0], o[4 * i + 1], p, p, vv.x, vv.y);
                    fma2(o[4 * i + 2], o[4 * i + 3], p, p, vv.z, vv.w);
                }
            }
        }
        __syncthreads();
    }

    // store partials (unnormalized o, running max m, running sum l)
    int base = (sp * HEADS + h) * NPIX + n;
    pm[base] = m;
    pl[base] = l;
    #pragma unroll
    for (int d = 0; d < 24; d++)
        po[((sp * HEADS + h) * HD + d) * NPIX + n] = o[d];
}

// ---------------- Kernel 5: combine split-KV partials ----------------
__global__ __launch_bounds__(256) void attn_combine_kernel(
        const float* __restrict__ po, const float* __restrict__ pm,
        const float* __restrict__ pl, float* __restrict__ out) {
    int idx = blockIdx.x * 256 + threadIdx.x;    // over HEADS*NPIX
    int h = idx >> 12;
    int n = idx & (NPIX - 1);

    float m = -1e30f;
    #pragma unroll
    for (int sp = 0; sp < SPLITS; sp++)
        m = fmaxf(m, pm[(sp * HEADS + h) * NPIX + n]);

    float w[SPLITS];
    float l = 0.f;
    #pragma unroll
    for (int sp = 0; sp < SPLITS; sp++) {
        w[sp] = ex2f_fast(pm[(sp * HEADS + h) * NPIX + n] - m);
        l = fmaf(pl[(sp * HEADS + h) * NPIX + n], w[sp], l);
    }
    float invl = 1.0f / l;

    #pragma unroll
    for (int d = 0; d < 24; d++) {
        float acc = 0.f;
        #pragma unroll
        for (int sp = 0; sp < SPLITS; sp++)
            acc = fmaf(po[((sp * HEADS + h) * HD + d) * NPIX + n], w[sp], acc);
        out[(h * HD + d) * NPIX + n] = acc * invl;
    }
}

// ---------------- launch ----------------
extern "C" void kernel_launch(void* const* d_in, const int* in_sizes, int n_in,
                              void* d_out, int out_size) {
    const float* x      = (const float*)d_in[0];   // [192,4096]
    const float* gamma  = (const float*)d_in[1];   // [192]
    const float* beta   = (const float*)d_in[2];   // [192]
    const float* w_qkv  = (const float*)d_in[3];   // [576,192]
    const float* w_dw   = (const float*)d_in[4];   // [576,9]
    const float* b_dw   = (const float*)d_in[5];   // [576]
    const float* w_proj = (const float*)d_in[6];   // [192,192]
    const float* temper = (const float*)d_in[7];   // [8]
    float* out = (float*)d_out;

    float *xln, *qkvb, *qkvdw, *att, *po, *pmv, *plv;
    cudaGetSymbolAddress((void**)&xln,   g_xln);
    cudaGetSymbolAddress((void**)&qkvb,  g_qkv);
    cudaGetSymbolAddress((void**)&qkvdw, g_qkvdw);
    cudaGetSymbolAddress((void**)&att,   g_att);
    cudaGetSymbolAddress((void**)&po,    g_po);
    cudaGetSymbolAddress((void**)&pmv,   g_pm);
    cudaGetSymbolAddress((void**)&plv,   g_pl);

    // 1. LayerNorm
    ln_kernel<<<NPIX / 256, 256>>>(x, gamma, beta, xln);

    // 2. qkv = w_qkv @ xln   [576,4096]
    {
        dim3 grid(NPIX / 64, QKV_CH / 64);
        gemm_kernel<<<grid, 256>>>(w_qkv, xln, nullptr, qkvb, QKV_CH, C_DIM, NPIX);
    }

    // 3. depthwise 3x3 + bias
    dwconv_kernel<<<(QKV_CH * NPIX) / 256, 256>>>(qkvb, w_dw, b_dw, qkvdw);

    // 4. attention partials (split-KV) then combine -> att [192,4096]
    {
        dim3 grid(NPIX / 256, HEADS, SPLITS);
        attn_part_kernel<<<grid, 256>>>(qkvdw, temper, po, pmv, plv);
        attn_combine_kernel<<<(HEADS * NPIX) / 256, 256>>>(po, pmv, plv, att);
    }

    // 5. out = w_proj @ att + x
    {
        dim3 grid(NPIX / 64, C_DIM / 64);
        gemm_kernel<<<grid, 256>>>(w_proj, att, x, out, C_DIM, C_DIM, NPIX);
    }
}

// round 5
// speedup vs baseline: 1.7593x; 1.2037x over previous
#include <cuda_runtime.h>
#include <cuda_bf16.h>

// Problem constants
#define C_DIM   192
#define HEADS   8
#define HD      24          // head dim = 192/8
#define HH      64
#define WW      64
#define NPIX    4096        // 64*64
#define QKV_CH  576         // 3*C
#define SPLITS  8
#define MCHUNK  (NPIX / SPLITS)   // 512

// ---------------- scratch (static device globals; no allocs) ----------------
__device__ float g_xln[C_DIM * NPIX];                 // 3 MB
__device__ float g_qkv[QKV_CH * NPIX];                // 9 MB
__device__ float g_qkvdw[QKV_CH * NPIX];              // 9 MB
__device__ float g_att[C_DIM * NPIX];                 // 3 MB
__device__ float g_po[SPLITS * HEADS * HD * NPIX];    // 25 MB partial outputs
__device__ float g_pm[SPLITS * HEADS * NPIX];         // partial max (log2 domain)
__device__ float g_pl[SPLITS * HEADS * NPIX];         // partial sum

// ---------------- small helpers ----------------
__device__ __forceinline__ float ex2f_fast(float x) {
    float r;
    asm("ex2.approx.f32 %0, %1;" : "=f"(r) : "f"(x));
    return r;
}

// packed fp32x2 fma: (x,y) += (ax,ay)*(bx,by)
__device__ __forceinline__ void fma2(float& x, float& y, float ax, float ay, float bx, float by) {
    asm("{\n\t"
        ".reg .b64 a, b, c;\n\t"
        "mov.b64 a, {%2, %3};\n\t"
        "mov.b64 b, {%4, %5};\n\t"
        "mov.b64 c, {%0, %1};\n\t"
        "fma.rn.f32x2 c, a, b, c;\n\t"
        "mov.b64 {%0, %1}, c;\n\t"
        "}"
        : "+f"(x), "+f"(y)
        : "f"(ax), "f"(ay), "f"(bx), "f"(by));
}

// packed fp32x2 scale: (x,y) *= a
__device__ __forceinline__ void mul2(float& x, float& y, float a) {
    asm("{\n\t"
        ".reg .b64 c, s;\n\t"
        "mov.b64 c, {%0, %1};\n\t"
        "mov.b64 s, {%2, %2};\n\t"
        "mul.rn.f32x2 c, c, s;\n\t"
        "mov.b64 {%0, %1}, c;\n\t"
        "}"
        : "+f"(x), "+f"(y)
        : "f"(a));
}

// ---------------- Kernel 1: per-pixel LayerNorm over channels ----------------
__global__ void ln_kernel(const float* __restrict__ x,
                          const float* __restrict__ gamma,
                          const float* __restrict__ beta,
                          float* __restrict__ xln) {
    int p = blockIdx.x * blockDim.x + threadIdx.x;
    if (p >= NPIX) return;
    float s = 0.f, s2 = 0.f;
    #pragma unroll 8
    for (int c = 0; c < C_DIM; c++) {
        float v = x[c * NPIX + p];
        s += v;
        s2 = fmaf(v, v, s2);
    }
    const float invC = 1.0f / (float)C_DIM;
    float mean = s * invC;
    float var = s2 * invC - mean * mean;
    float inv = rsqrtf(var + 1e-5f);
    #pragma unroll 8
    for (int c = 0; c < C_DIM; c++) {
        float v = (x[c * NPIX + p] - mean) * inv;
        xln[c * NPIX + p] = fmaf(v, gamma[c], beta[c]);
    }
}

// ---------------- Kernel 2: GEMM  Y[O,N] = W[O,C] @ X[C,N] (+ optional residual) ----
__global__ __launch_bounds__(256) void gemm_kernel(
        const float* __restrict__ W, const float* __restrict__ X,
        const float* __restrict__ resid, float* __restrict__ Y,
        int O, int C, int N) {
    __shared__ __align__(16) float As[16][68];   // [k][o], padded
    __shared__ __align__(16) float Bs[16][64];   // [k][n]
    int tid = threadIdx.x;
    int tx = tid & 15;       // N dir
    int ty = tid >> 4;       // O dir
    int o0 = blockIdx.y * 64;
    int n0 = blockIdx.x * 64;

    float acc[4][4];
    #pragma unroll
    for (int i = 0; i < 4; i++)
        #pragma unroll
        for (int j = 0; j < 4; j++) acc[i][j] = 0.f;

    for (int k0 = 0; k0 < C; k0 += 16) {
        {
            int row = tid >> 2;
            int col = (tid & 3) * 4;
            float4 a = *(const float4*)&W[(o0 + row) * C + k0 + col];
            As[col + 0][row] = a.x;
            As[col + 1][row] = a.y;
            As[col + 2][row] = a.z;
            As[col + 3][row] = a.w;
        }
        {
            int row = tid >> 4;
            int col = (tid & 15) * 4;
            *(float4*)&Bs[row][col] = *(const float4*)&X[(k0 + row) * N + n0 + col];
        }
        __syncthreads();
        #pragma unroll
        for (int k = 0; k < 16; k++) {
            float4 a4 = *(const float4*)&As[k][ty * 4];
            float4 b4 = *(const float4*)&Bs[k][tx * 4];
            float a[4] = {a4.x, a4.y, a4.z, a4.w};
            float b[4] = {b4.x, b4.y, b4.z, b4.w};
            #pragma unroll
            for (int i = 0; i < 4; i++)
                #pragma unroll
                for (int j = 0; j < 4; j++)
                    acc[i][j] = fmaf(a[i], b[j], acc[i][j]);
        }
        __syncthreads();
    }

    #pragma unroll
    for (int i = 0; i < 4; i++) {
        int o = o0 + ty * 4 + i;
        int n = n0 + tx * 4;
        float4 r = make_float4(acc[i][0], acc[i][1], acc[i][2], acc[i][3]);
        if (resid) {
            float4 rv = *(const float4*)&resid[o * N + n];
            r.x += rv.x; r.y += rv.y; r.z += rv.z; r.w += rv.w;
        }
        *(float4*)&Y[o * N + n] = r;
    }
}

// ---------------- Kernel 3: depthwise 3x3 conv + bias ----------------
__global__ void dwconv_kernel(const float* __restrict__ in,
                              const float* __restrict__ w,
                              const float* __restrict__ b,
                              float* __restrict__ out) {
    int idx = blockIdx.x * blockDim.x + threadIdx.x;
    if (idx >= QKV_CH * NPIX) return;
    int xx = idx & (WW - 1);
    int yy = (idx >> 6) & (HH - 1);
    int ch = idx >> 12;
    const float* wp = &w[ch * 9];
    const float* base = &in[ch * NPIX];
    float acc = b[ch];
    #pragma unroll
    for (int dy = -1; dy <= 1; dy++) {
        int y2 = yy + dy;
        if (y2 < 0 || y2 >= HH) continue;
        #pragma unroll
        for (int dx = -1; dx <= 1; dx++) {
            int x2 = xx + dx;
            if (x2 < 0 || x2 >= WW) continue;
            acc = fmaf(base[y2 * WW + x2], wp[(dy + 1) * 3 + (dx + 1)], acc);
        }
    }
    out[idx] = acc;
}

// ---------------- Kernel 4: flash attention partials (split-KV, 2 queries/thread) ----
// Each block: 128 threads x 2 queries = 256 queries x one KV chunk (512 positions).
// K/V float4 register loads shared between both queries -> halves LDS per query.
#define ATT_TILE 64
__global__ __launch_bounds__(128, 3) void attn_part_kernel(
        const float* __restrict__ qkv, const float* __restrict__ temp,
        float* __restrict__ po, float* __restrict__ pm, float* __restrict__ pl) {
    __shared__ __align__(16) float Ks[ATT_TILE][24];
    __shared__ __align__(16) float Vs[ATT_TILE][24];

    int h = blockIdx.y;
    int sp = blockIdx.z;
    int na = blockIdx.x * 256 + threadIdx.x;   // query A
    int nb = na + 128;                          // query B
    const float scale = temp[h] * 1.4426950408889634f;  // temperature * log2(e)

    float qa[24], qb[24];
    #pragma unroll
    for (int d = 0; d < 24; d++) {
        qa[d] = qkv[(h * HD + d) * NPIX + na] * scale;
        qb[d] = qkv[(h * HD + d) * NPIX + nb] * scale;
    }

    float oa[24], ob[24];
    #pragma unroll
    for (int d = 0; d < 24; d++) { oa[d] = 0.f; ob[d] = 0.f; }
    float ma = -1e30f, la = 0.f;
    float mb = -1e30f, lb = 0.f;

    const float* kg = &qkv[(C_DIM + h * HD) * NPIX];
    const float* vg = &qkv[(2 * C_DIM + h * HD) * NPIX];

    const int mbeg = sp * MCHUNK;
    const int mend = mbeg + MCHUNK;

    for (int m0 = mbeg; m0 < mend; m0 += ATT_TILE) {
        // cooperative load, global coalesced, smem [j][d]
        #pragma unroll
        for (int e = threadIdx.x; e < ATT_TILE * 24; e += 128) {
            int d = e >> 6;
            int j = e & (ATT_TILE - 1);
            Ks[j][d] = kg[d * NPIX + m0 + j];
            Vs[j][d] = vg[d * NPIX + m0 + j];
        }
        __syncthreads();

        #pragma unroll 1
        for (int c0 = 0; c0 < ATT_TILE; c0 += 8) {
            float sa[8], sb[8];
            // S = q . K for both queries, K float4 loads shared
            #pragma unroll
            for (int jj = 0; jj < 8; jj++) {
                const float4* kp = (const float4*)&Ks[c0 + jj][0];
                float ax = 0.f, ay = 0.f;
                float bx = 0.f, by = 0.f;
                #pragma unroll
                for (int i = 0; i < 6; i++) {
                    float4 kv = kp[i];
                    fma2(ax, ay, qa[4 * i + 0], qa[4 * i + 1], kv.x, kv.y);
                    fma2(ax, ay, qa[4 * i + 2], qa[4 * i + 3], kv.z, kv.w);
                    fma2(bx, by, qb[4 * i + 0], qb[4 * i + 1], kv.x, kv.y);
                    fma2(bx, by, qb[4 * i + 2], qb[4 * i + 3], kv.z, kv.w);
                }
                sa[jj] = ax + ay;
                sb[jj] = bx + by;
            }
            // online softmax update (per query)
            float mxa = ma, mxb = mb;
            #pragma unroll
            for (int jj = 0; jj < 8; jj++) {
                mxa = fmaxf(mxa, sa[jj]);
                mxb = fmaxf(mxb, sb[jj]);
            }
            float alA = ex2f_fast(ma - mxa);
            float alB = ex2f_fast(mb - mxb);
            ma = mxa; mb = mxb;
            la *= alA; lb *= alB;
            #pragma unroll
            for (int i = 0; i < 12; i++) {
                mul2(oa[2 * i], oa[2 * i + 1], alA);
                mul2(ob[2 * i], ob[2 * i + 1], alB);
            }
            // accumulate P @ V, V float4 loads shared
            #pragma unroll
            for (int jj = 0; jj < 8; jj++) {
                float pA = ex2f_fast(sa[jj] - ma);
                float pB = ex2f_fast(sb[jj] - mb);
                la += pA;
                lb += pB;
                const float4* vp = (const float4*)&Vs[c0 + jj][0];
                #pragma unroll
                for (int i = 0; i < 6; i++) {
                    float4 vv = vp[i];
                    fma2(oa[4 * i + 0], oa[4 * i + 1], pA, pA, vv.x, vv.y);
                    fma2(oa[4 * i + 2], oa[4 * i + 3], pA, pA, vv.z, vv.w);
                    fma2(ob[4 * i + 0], ob[4 * i + 1], pB, pB, vv.x, vv.y);
                    fma2(ob[4 * i + 2], ob[4 * i + 3], pB, pB, vv.z, vv.w);
                }
            }
        }
        __syncthreads();
    }

    // store partials (unnormalized o, running max m, running sum l)
    int baseA = (sp * HEADS + h) * NPIX + na;
    int baseB = (sp * HEADS + h) * NPIX + nb;
    pm[baseA] = ma; pm[baseB] = mb;
    pl[baseA] = la; pl[baseB] = lb;
    #pragma unroll
    for (int d = 0; d < 24; d++) {
        po[((sp * HEADS + h) * HD + d) * NPIX + na] = oa[d];
        po[((sp * HEADS + h) * HD + d) * NPIX + nb] = ob[d];
    }
}

// ---------------- Kernel 5: combine split-KV partials ----------------
__global__ __launch_bounds__(256) void attn_combine_kernel(
        const float* __restrict__ po, const float* __restrict__ pm,
        const float* __restrict__ pl, float* __restrict__ out) {
    int idx = blockIdx.x * 256 + threadIdx.x;    // over HEADS*NPIX
    int h = idx >> 12;
    int n = idx & (NPIX - 1);

    float m = -1e30f;
    #pragma unroll
    for (int sp = 0; sp < SPLITS; sp++)
        m = fmaxf(m, pm[(sp * HEADS + h) * NPIX + n]);

    float w[SPLITS];
    float l = 0.f;
    #pragma unroll
    for (int sp = 0; sp < SPLITS; sp++) {
        w[sp] = ex2f_fast(pm[(sp * HEADS + h) * NPIX + n] - m);
        l = fmaf(pl[(sp * HEADS + h) * NPIX + n], w[sp], l);
    }
    float invl = 1.0f / l;

    #pragma unroll
    for (int d = 0; d < 24; d++) {
        float acc = 0.f;
        #pragma unroll
        for (int sp = 0; sp < SPLITS; sp++)
            acc = fmaf(po[((sp * HEADS + h) * HD + d) * NPIX + n], w[sp], acc);
        out[(h * HD + d) * NPIX + n] = acc * invl;
    }
}

// ---------------- launch ----------------
extern "C" void kernel_launch(void* const* d_in, const int* in_sizes, int n_in,
                              void* d_out, int out_size) {
    const float* x      = (const float*)d_in[0];   // [192,4096]
    const float* gamma  = (const float*)d_in[1];   // [192]
    const float* beta   = (const float*)d_in[2];   // [192]
    const float* w_qkv  = (const float*)d_in[3];   // [576,192]
    const float* w_dw   = (const float*)d_in[4];   // [576,9]
    const float* b_dw   = (const float*)d_in[5];   // [576]
    const float* w_proj = (const float*)d_in[6];   // [192,192]
    const float* temper = (const float*)d_in[7];   // [8]
    float* out = (float*)d_out;

    float *xln, *qkvb, *qkvdw, *att, *po, *pmv, *plv;
    cudaGetSymbolAddress((void**)&xln,   g_xln);
    cudaGetSymbolAddress((void**)&qkvb,  g_qkv);
    cudaGetSymbolAddress((void**)&qkvdw, g_qkvdw);
    cudaGetSymbolAddress((void**)&att,   g_att);
    cudaGetSymbolAddress((void**)&po,    g_po);
    cudaGetSymbolAddress((void**)&pmv,   g_pm);
    cudaGetSymbolAddress((void**)&plv,   g_pl);

    // 1. LayerNorm
    ln_kernel<<<NPIX / 256, 256>>>(x, gamma, beta, xln);

    // 2. qkv = w_qkv @ xln   [576,4096]
    {
        dim3 grid(NPIX / 64, QKV_CH / 64);
        gemm_kernel<<<grid, 256>>>(w_qkv, xln, nullptr, qkvb, QKV_CH, C_DIM, NPIX);
    }

    // 3. depthwise 3x3 + bias
    dwconv_kernel<<<(QKV_CH * NPIX) / 256, 256>>>(qkvb, w_dw, b_dw, qkvdw);

    // 4. attention partials (split-KV) then combine -> att [192,4096]
    {
        dim3 grid(NPIX / 256, HEADS, SPLITS);
        attn_part_kernel<<<grid, 128>>>(qkvdw, temper, po, pmv, plv);
        attn_combine_kernel<<<(HEADS * NPIX) / 256, 256>>>(po, pmv, plv, att);
    }

    // 5. out = w_proj @ att + x
    {
        dim3 grid(NPIX / 64, C_DIM / 64);
        gemm_kernel<<<grid, 256>>>(w_proj, att, x, out, C_DIM, C_DIM, NPIX);
    }
}

// round 6
// speedup vs baseline: 3.2259x; 1.8337x over previous
#include <cuda_runtime.h>
#include <cuda_fp16.h>
#include <cuda_bf16.h>
#include <cstdint>

// Problem constants
#define C_DIM   192
#define HEADS   8
#define HD      24          // head dim = 192/8
#define HH      64
#define WW      64
#define NPIX    4096        // 64*64
#define QKV_CH  576         // 3*C

// ---------------- scratch (static device globals; no allocs) ----------------
__device__ float g_xln[C_DIM * NPIX];                 // 3 MB
__device__ float g_qkv[QKV_CH * NPIX];                // 9 MB
__device__ float g_qkvdw[QKV_CH * NPIX];              // 9 MB
__device__ float g_att[C_DIM * NPIX];                 // 3 MB

// ---------------- small helpers ----------------
__device__ __forceinline__ float ex2f_fast(float x) {
    float r;
    asm("ex2.approx.f32 %0, %1;" : "=f"(r) : "f"(x));
    return r;
}

// ---------------- Kernel 1: per-pixel LayerNorm over channels ----------------
__global__ void ln_kernel(const float* __restrict__ x,
                          const float* __restrict__ gamma,
                          const float* __restrict__ beta,
                          float* __restrict__ xln) {
    int p = blockIdx.x * blockDim.x + threadIdx.x;
    if (p >= NPIX) return;
    float s = 0.f, s2 = 0.f;
    #pragma unroll 8
    for (int c = 0; c < C_DIM; c++) {
        float v = x[c * NPIX + p];
        s += v;
        s2 = fmaf(v, v, s2);
    }
    const float invC = 1.0f / (float)C_DIM;
    float mean = s * invC;
    float var = s2 * invC - mean * mean;
    float inv = rsqrtf(var + 1e-5f);
    #pragma unroll 8
    for (int c = 0; c < C_DIM; c++) {
        float v = (x[c * NPIX + p] - mean) * inv;
        xln[c * NPIX + p] = fmaf(v, gamma[c], beta[c]);
    }
}

// ---------------- Kernel 2: GEMM  Y[O,N] = W[O,C] @ X[C,N] (+ optional residual) ----
__global__ __launch_bounds__(256) void gemm_kernel(
        const float* __restrict__ W, const float* __restrict__ X,
        const float* __restrict__ resid, float* __restrict__ Y,
        int O, int C, int N) {
    __shared__ __align__(16) float As[16][68];   // [k][o], padded
    __shared__ __align__(16) float Bs[16][64];   // [k][n]
    int tid = threadIdx.x;
    int tx = tid & 15;       // N dir
    int ty = tid >> 4;       // O dir
    int o0 = blockIdx.y * 64;
    int n0 = blockIdx.x * 64;

    float acc[4][4];
    #pragma unroll
    for (int i = 0; i < 4; i++)
        #pragma unroll
        for (int j = 0; j < 4; j++) acc[i][j] = 0.f;

    for (int k0 = 0; k0 < C; k0 += 16) {
        {
            int row = tid >> 2;
            int col = (tid & 3) * 4;
            float4 a = *(const float4*)&W[(o0 + row) * C + k0 + col];
            As[col + 0][row] = a.x;
            As[col + 1][row] = a.y;
            As[col + 2][row] = a.z;
            As[col + 3][row] = a.w;
        }
        {
            int row = tid >> 4;
            int col = (tid & 15) * 4;
            *(float4*)&Bs[row][col] = *(const float4*)&X[(k0 + row) * N + n0 + col];
        }
        __syncthreads();
        #pragma unroll
        for (int k = 0; k < 16; k++) {
            float4 a4 = *(const float4*)&As[k][ty * 4];
            float4 b4 = *(const float4*)&Bs[k][tx * 4];
            float a[4] = {a4.x, a4.y, a4.z, a4.w};
            float b[4] = {b4.x, b4.y, b4.z, b4.w};
            #pragma unroll
            for (int i = 0; i < 4; i++)
                #pragma unroll
                for (int j = 0; j < 4; j++)
                    acc[i][j] = fmaf(a[i], b[j], acc[i][j]);
        }
        __syncthreads();
    }

    #pragma unroll
    for (int i = 0; i < 4; i++) {
        int o = o0 + ty * 4 + i;
        int n = n0 + tx * 4;
        float4 r = make_float4(acc[i][0], acc[i][1], acc[i][2], acc[i][3]);
        if (resid) {
            float4 rv = *(const float4*)&resid[o * N + n];
            r.x += rv.x; r.y += rv.y; r.z += rv.z; r.w += rv.w;
        }
        *(float4*)&Y[o * N + n] = r;
    }
}

// ---------------- Kernel 3: depthwise 3x3 conv + bias ----------------
__global__ void dwconv_kernel(const float* __restrict__ in,
                              const float* __restrict__ w,
                              const float* __restrict__ b,
                              float* __restrict__ out) {
    int idx = blockIdx.x * blockDim.x + threadIdx.x;
    if (idx >= QKV_CH * NPIX) return;
    int xx = idx & (WW - 1);
    int yy = (idx >> 6) & (HH - 1);
    int ch = idx >> 12;
    const float* wp = &w[ch * 9];
    const float* base = &in[ch * NPIX];
    float acc = b[ch];
    #pragma unroll
    for (int dy = -1; dy <= 1; dy++) {
        int y2 = yy + dy;
        if (y2 < 0 || y2 >= HH) continue;
        #pragma unroll
        for (int dx = -1; dx <= 1; dx++) {
            int x2 = xx + dx;
            if (x2 < 0 || x2 >= WW) continue;
            acc = fmaf(base[y2 * WW + x2], wp[(dy + 1) * 3 + (dx + 1)], acc);
        }
    }
    out[idx] = acc;
}

// ---------------- Kernel 4: tensor-core flash attention (mma.sync m16n8k16) ----
// CTA: 256 threads = 8 warps, 128 queries (16/warp), loops full 4096 keys
// in chunks of 64. QK^T compensated (q,k split hi+lo fp16): error ~2^-21.
// PV with fp16 P,V and fp32 accumulate.
#define ATT_Q  128
#define ATT_K  64
#define NCHUNK (NPIX / ATT_K)

// smem layout (in halves). K rows padded to 40 (conflict-free quad reads),
// V rows padded to 72.
#define SQ_H 0                       // Qh [128][40]
#define SQ_L (SQ_H + 128 * 40)       // Ql [128][40]
#define SK_H (SQ_L + 128 * 40)       // Kh [64][40]
#define SK_L (SK_H + 64 * 40)        // Kl [64][40]
#define SV   (SK_L + 64 * 40)        // V  [24][72]
#define SM_TOT (SV + 24 * 72)        // 17088 halves = 34176 B

__device__ __forceinline__ void mma16816(float c[4], const uint32_t a[4],
                                         uint32_t b0, uint32_t b1) {
    asm volatile(
        "mma.sync.aligned.m16n8k16.row.col.f32.f16.f16.f32 "
        "{%0,%1,%2,%3}, {%4,%5,%6,%7}, {%8,%9}, {%0,%1,%2,%3};"
        : "+f"(c[0]), "+f"(c[1]), "+f"(c[2]), "+f"(c[3])
        : "r"(a[0]), "r"(a[1]), "r"(a[2]), "r"(a[3]), "r"(b0), "r"(b1));
}

__device__ __forceinline__ uint32_t packh2(float x, float y) {
    __half2 h = __floats2half2_rn(x, y);   // low <- x, high <- y
    return *(uint32_t*)&h;
}

__global__ __launch_bounds__(256, 2) void attn_mma_kernel(
        const float* __restrict__ qkv, const float* __restrict__ temp,
        float* __restrict__ att) {
    __shared__ __half sm[SM_TOT];
    const int tid = threadIdx.x;
    const int lane = tid & 31;
    const int warp = tid >> 5;
    const int g = lane >> 2;      // row group 0..7
    const int t = lane & 3;       // thread-in-group

    const int h = blockIdx.y;
    const int q0 = blockIdx.x * ATT_Q;
    const float scale = temp[h] * 1.4426950408889634f;  // temperature * log2(e)

    const float* qg = qkv + (h * HD) * NPIX;
    const float* kg = qkv + (C_DIM + h * HD) * NPIX;
    const float* vg = qkv + (2 * C_DIM + h * HD) * NPIX;

    // zero smem (padding columns must stay zero)
    for (int i = tid; i < SM_TOT; i += 256) sm[i] = __ushort_as_half(0);
    __syncthreads();

    // stage Q (scaled, hi/lo split), layout [q][40]
    #pragma unroll
    for (int i = 0; i < 12; i++) {
        int e = tid + i * 256;            // 128*24 = 3072
        int d = e >> 7;
        int qq = e & 127;
        float v = qg[d * NPIX + q0 + qq] * scale;
        __half hi = __float2half_rn(v);
        __half lo = __float2half_rn(v - __half2float(hi));
        sm[SQ_H + qq * 40 + d] = hi;
        sm[SQ_L + qq * 40 + d] = lo;
    }
    __syncthreads();

    // load Q A-fragments (2 k-steps over d 0..31, cols 24..31 are zero pad)
    uint32_t aqh[2][4], aql[2][4];
    const int qr = warp * 16 + g;
    #pragma unroll
    for (int ks = 0; ks < 2; ks++) {
        int db = ks * 16 + t * 2;
        aqh[ks][0] = *(const uint32_t*)&sm[SQ_H + qr * 40 + db];
        aqh[ks][1] = *(const uint32_t*)&sm[SQ_H + (qr + 8) * 40 + db];
        aqh[ks][2] = *(const uint32_t*)&sm[SQ_H + qr * 40 + db + 8];
        aqh[ks][3] = *(const uint32_t*)&sm[SQ_H + (qr + 8) * 40 + db + 8];
        aql[ks][0] = *(const uint32_t*)&sm[SQ_L + qr * 40 + db];
        aql[ks][1] = *(const uint32_t*)&sm[SQ_L + (qr + 8) * 40 + db];
        aql[ks][2] = *(const uint32_t*)&sm[SQ_L + qr * 40 + db + 8];
        aql[ks][3] = *(const uint32_t*)&sm[SQ_L + (qr + 8) * 40 + db + 8];
    }

    float out[3][4];
    #pragma unroll
    for (int i = 0; i < 3; i++)
        #pragma unroll
        for (int j = 0; j < 4; j++) out[i][j] = 0.f;
    float m_a = -1e30f, m_b = -1e30f;   // row maxes (rows g, g+8) in log2 units
    float l_a = 0.f, l_b = 0.f;

    // prefetch chunk 0 (K and V) into registers
    float kbuf[6], vbuf[6];
    {
        #pragma unroll
        for (int i = 0; i < 6; i++) {
            int e = tid + i * 256;        // 64*24 = 1536
            int d = e >> 6, j = e & 63;
            kbuf[i] = kg[d * NPIX + j];
            vbuf[i] = vg[d * NPIX + j];
        }
    }

    for (int ch = 0; ch < NCHUNK; ch++) {
        __syncthreads();   // previous chunk's compute done
        // store staged regs -> smem (K hi/lo [key][40], V [d][72])
        #pragma unroll
        for (int i = 0; i < 6; i++) {
            int e = tid + i * 256;
            int d = e >> 6, j = e & 63;
            float kv = kbuf[i];
            __half hi = __float2half_rn(kv);
            sm[SK_H + j * 40 + d] = hi;
            sm[SK_L + j * 40 + d] = __float2half_rn(kv - __half2float(hi));
            sm[SV + d * 72 + j] = __float2half_rn(vbuf[i]);
        }
        __syncthreads();
        // prefetch next chunk
        if (ch + 1 < NCHUNK) {
            int m0 = (ch + 1) * ATT_K;
            #pragma unroll
            for (int i = 0; i < 6; i++) {
                int e = tid + i * 256;
                int d = e >> 6, j = e & 63;
                kbuf[i] = kg[d * NPIX + m0 + j];
                vbuf[i] = vg[d * NPIX + m0 + j];
            }
        }

        // ---- S = Q K^T (compensated), 8 n-tiles of 8 keys ----
        float s[8][4];
        #pragma unroll
        for (int nt = 0; nt < 8; nt++) {
            s[nt][0] = s[nt][1] = s[nt][2] = s[nt][3] = 0.f;
            int kr = nt * 8 + g;
            #pragma unroll
            for (int ks = 0; ks < 2; ks++) {
                int db = ks * 16 + t * 2;
                uint32_t bh0 = *(const uint32_t*)&sm[SK_H + kr * 40 + db];
                uint32_t bh1 = *(const uint32_t*)&sm[SK_H + kr * 40 + db + 8];
                uint32_t bl0 = *(const uint32_t*)&sm[SK_L + kr * 40 + db];
                uint32_t bl1 = *(const uint32_t*)&sm[SK_L + kr * 40 + db + 8];
                mma16816(s[nt], aqh[ks], bh0, bh1);
                mma16816(s[nt], aqh[ks], bl0, bl1);
                mma16816(s[nt], aql[ks], bh0, bh1);
            }
        }

        // ---- online softmax (log2 domain) ----
        float ra = -1e30f, rb = -1e30f;
        #pragma unroll
        for (int nt = 0; nt < 8; nt++) {
            ra = fmaxf(ra, fmaxf(s[nt][0], s[nt][1]));
            rb = fmaxf(rb, fmaxf(s[nt][2], s[nt][3]));
        }
        ra = fmaxf(ra, __shfl_xor_sync(0xffffffffu, ra, 1));
        ra = fmaxf(ra, __shfl_xor_sync(0xffffffffu, ra, 2));
        rb = fmaxf(rb, __shfl_xor_sync(0xffffffffu, rb, 1));
        rb = fmaxf(rb, __shfl_xor_sync(0xffffffffu, rb, 2));
        float nma = fmaxf(m_a, ra);
        float nmb = fmaxf(m_b, rb);
        float ala = ex2f_fast(m_a - nma);
        float alb = ex2f_fast(m_b - nmb);
        m_a = nma; m_b = nmb;
        l_a *= ala; l_b *= alb;
        #pragma unroll
        for (int dnt = 0; dnt < 3; dnt++) {
            out[dnt][0] *= ala; out[dnt][1] *= ala;
            out[dnt][2] *= alb; out[dnt][3] *= alb;
        }
        float sa = 0.f, sb = 0.f;
        #pragma unroll
        for (int nt = 0; nt < 8; nt++) {
            s[nt][0] = ex2f_fast(s[nt][0] - m_a);
            s[nt][1] = ex2f_fast(s[nt][1] - m_a);
            s[nt][2] = ex2f_fast(s[nt][2] - m_b);
            s[nt][3] = ex2f_fast(s[nt][3] - m_b);
            sa += s[nt][0] + s[nt][1];
            sb += s[nt][2] + s[nt][3];
        }
        sa += __shfl_xor_sync(0xffffffffu, sa, 1);
        sa += __shfl_xor_sync(0xffffffffu, sa, 2);
        sb += __shfl_xor_sync(0xffffffffu, sb, 1);
        sb += __shfl_xor_sync(0xffffffffu, sb, 2);
        l_a += sa; l_b += sb;

        // ---- out += P V  (P: C-layout == A-layout trick) ----
        #pragma unroll
        for (int kv = 0; kv < 4; kv++) {
            uint32_t pa[4];
            pa[0] = packh2(s[2 * kv][0],     s[2 * kv][1]);
            pa[1] = packh2(s[2 * kv][2],     s[2 * kv][3]);
            pa[2] = packh2(s[2 * kv + 1][0], s[2 * kv + 1][1]);
            pa[3] = packh2(s[2 * kv + 1][2], s[2 * kv + 1][3]);
            #pragma unroll
            for (int dnt = 0; dnt < 3; dnt++) {
                int vr = dnt * 8 + g;
                uint32_t bv0 = *(const uint32_t*)&sm[SV + vr * 72 + kv * 16 + t * 2];
                uint32_t bv1 = *(const uint32_t*)&sm[SV + vr * 72 + kv * 16 + t * 2 + 8];
                mma16816(out[dnt], pa, bv0, bv1);
            }
        }
    }

    // epilogue: normalize and store
    float inva = 1.0f / l_a;
    float invb = 1.0f / l_b;
    int qa = q0 + warp * 16 + g;
    int qb = qa + 8;
    #pragma unroll
    for (int dnt = 0; dnt < 3; dnt++) {
        int c0 = h * HD + dnt * 8 + t * 2;
        att[c0 * NPIX + qa]       = out[dnt][0] * inva;
        att[(c0 + 1) * NPIX + qa] = out[dnt][1] * inva;
        att[c0 * NPIX + qb]       = out[dnt][2] * invb;
        att[(c0 + 1) * NPIX + qb] = out[dnt][3] * invb;
    }
}

// ---------------- launch ----------------
extern "C" void kernel_launch(void* const* d_in, const int* in_sizes, int n_in,
                              void* d_out, int out_size) {
    const float* x      = (const float*)d_in[0];   // [192,4096]
    const float* gamma  = (const float*)d_in[1];   // [192]
    const float* beta   = (const float*)d_in[2];   // [192]
    const float* w_qkv  = (const float*)d_in[3];   // [576,192]
    const float* w_dw   = (const float*)d_in[4];   // [576,9]
    const float* b_dw   = (const float*)d_in[5];   // [576]
    const float* w_proj = (const float*)d_in[6];   // [192,192]
    const float* temper = (const float*)d_in[7];   // [8]
    float* out = (float*)d_out;

    float *xln, *qkvb, *qkvdw, *att;
    cudaGetSymbolAddress((void**)&xln,   g_xln);
    cudaGetSymbolAddress((void**)&qkvb,  g_qkv);
    cudaGetSymbolAddress((void**)&qkvdw, g_qkvdw);
    cudaGetSymbolAddress((void**)&att,   g_att);

    // 1. LayerNorm
    ln_kernel<<<NPIX / 256, 256>>>(x, gamma, beta, xln);

    // 2. qkv = w_qkv @ xln   [576,4096]
    {
        dim3 grid(NPIX / 64, QKV_CH / 64);
        gemm_kernel<<<grid, 256>>>(w_qkv, xln, nullptr, qkvb, QKV_CH, C_DIM, NPIX);
    }

    // 3. depthwise 3x3 + bias
    dwconv_kernel<<<(QKV_CH * NPIX) / 256, 256>>>(qkvb, w_dw, b_dw, qkvdw);

    // 4. tensor-core flash attention -> att [192,4096]
    {
        dim3 grid(NPIX / ATT_Q, HEADS);
        attn_mma_kernel<<<grid, 256>>>(qkvdw, temper, att);
    }

    // 5. out = w_proj @ att + x
    {
        dim3 grid(NPIX / 64, C_DIM / 64);
        gemm_kernel<<<grid, 256>>>(w_proj, att, x, out, C_DIM, C_DIM, NPIX);
    }
}

// round 7
// speedup vs baseline: 3.5251x; 1.0927x over previous
#include <cuda_runtime.h>
#include <cuda_fp16.h>
#include <cuda_bf16.h>
#include <cstdint>

// Problem constants
#define C_DIM   192
#define HEADS   8
#define HD      24          // head dim = 192/8
#define HH      64
#define WW      64
#define NPIX    4096        // 64*64
#define QKV_CH  576         // 3*C

// ---------------- scratch (static device globals; no allocs) ----------------
__device__ float g_xln[C_DIM * NPIX];                 // 3 MB
__device__ float g_qkv[QKV_CH * NPIX];                // 9 MB
__device__ float g_qkvdw[QKV_CH * NPIX];              // 9 MB
__device__ float g_att[C_DIM * NPIX];                 // 3 MB

// ---------------- small helpers ----------------
__device__ __forceinline__ float ex2f_fast(float x) {
    float r;
    asm("ex2.approx.f32 %0, %1;" : "=f"(r) : "f"(x));
    return r;
}

// ---------------- Kernel 1: per-pixel LayerNorm over channels ----------------
__global__ void ln_kernel(const float* __restrict__ x,
                          const float* __restrict__ gamma,
                          const float* __restrict__ beta,
                          float* __restrict__ xln) {
    int p = blockIdx.x * blockDim.x + threadIdx.x;
    if (p >= NPIX) return;
    float s = 0.f, s2 = 0.f;
    #pragma unroll 8
    for (int c = 0; c < C_DIM; c++) {
        float v = x[c * NPIX + p];
        s += v;
        s2 = fmaf(v, v, s2);
    }
    const float invC = 1.0f / (float)C_DIM;
    float mean = s * invC;
    float var = s2 * invC - mean * mean;
    float inv = rsqrtf(var + 1e-5f);
    #pragma unroll 8
    for (int c = 0; c < C_DIM; c++) {
        float v = (x[c * NPIX + p] - mean) * inv;
        xln[c * NPIX + p] = fmaf(v, gamma[c], beta[c]);
    }
}

// ---------------- Kernel 2: GEMM  Y[O,N] = W[O,C] @ X[C,N] (+ optional residual) ----
__global__ __launch_bounds__(256) void gemm_kernel(
        const float* __restrict__ W, const float* __restrict__ X,
        const float* __restrict__ resid, float* __restrict__ Y,
        int O, int C, int N) {
    __shared__ __align__(16) float As[16][68];   // [k][o], padded
    __shared__ __align__(16) float Bs[16][64];   // [k][n]
    int tid = threadIdx.x;
    int tx = tid & 15;       // N dir
    int ty = tid >> 4;       // O dir
    int o0 = blockIdx.y * 64;
    int n0 = blockIdx.x * 64;

    float acc[4][4];
    #pragma unroll
    for (int i = 0; i < 4; i++)
        #pragma unroll
        for (int j = 0; j < 4; j++) acc[i][j] = 0.f;

    for (int k0 = 0; k0 < C; k0 += 16) {
        {
            int row = tid >> 2;
            int col = (tid & 3) * 4;
            float4 a = *(const float4*)&W[(o0 + row) * C + k0 + col];
            As[col + 0][row] = a.x;
            As[col + 1][row] = a.y;
            As[col + 2][row] = a.z;
            As[col + 3][row] = a.w;
        }
        {
            int row = tid >> 4;
            int col = (tid & 15) * 4;
            *(float4*)&Bs[row][col] = *(const float4*)&X[(k0 + row) * N + n0 + col];
        }
        __syncthreads();
        #pragma unroll
        for (int k = 0; k < 16; k++) {
            float4 a4 = *(const float4*)&As[k][ty * 4];
            float4 b4 = *(const float4*)&Bs[k][tx * 4];
            float a[4] = {a4.x, a4.y, a4.z, a4.w};
            float b[4] = {b4.x, b4.y, b4.z, b4.w};
            #pragma unroll
            for (int i = 0; i < 4; i++)
                #pragma unroll
                for (int j = 0; j < 4; j++)
                    acc[i][j] = fmaf(a[i], b[j], acc[i][j]);
        }
        __syncthreads();
    }

    #pragma unroll
    for (int i = 0; i < 4; i++) {
        int o = o0 + ty * 4 + i;
        int n = n0 + tx * 4;
        float4 r = make_float4(acc[i][0], acc[i][1], acc[i][2], acc[i][3]);
        if (resid) {
            float4 rv = *(const float4*)&resid[o * N + n];
            r.x += rv.x; r.y += rv.y; r.z += rv.z; r.w += rv.w;
        }
        *(float4*)&Y[o * N + n] = r;
    }
}

// ---------------- Kernel 3: depthwise 3x3 conv + bias ----------------
__global__ void dwconv_kernel(const float* __restrict__ in,
                              const float* __restrict__ w,
                              const float* __restrict__ b,
                              float* __restrict__ out) {
    int idx = blockIdx.x * blockDim.x + threadIdx.x;
    if (idx >= QKV_CH * NPIX) return;
    int xx = idx & (WW - 1);
    int yy = (idx >> 6) & (HH - 1);
    int ch = idx >> 12;
    const float* wp = &w[ch * 9];
    const float* base = &in[ch * NPIX];
    float acc = b[ch];
    #pragma unroll
    for (int dy = -1; dy <= 1; dy++) {
        int y2 = yy + dy;
        if (y2 < 0 || y2 >= HH) continue;
        #pragma unroll
        for (int dx = -1; dx <= 1; dx++) {
            int x2 = xx + dx;
            if (x2 < 0 || x2 >= WW) continue;
            acc = fmaf(base[y2 * WW + x2], wp[(dy + 1) * 3 + (dx + 1)], acc);
        }
    }
    out[idx] = acc;
}

// ---------------- Kernel 4: tensor-core flash attention (mma + ldmatrix) ----
// CTA: 256 threads = 8 warps, 128 queries (16/warp), loops full 4096 keys
// in chunks of 64. QK^T compensated (q,k split hi+lo fp16): error ~2^-21.
// PV with fp16 P,V and fp32 accumulate. All fragment loads via ldmatrix.x4.
#define ATT_Q  128
#define ATT_K  64
#define NCHUNK (NPIX / ATT_K)

// smem layout (in halves). K/Q rows padded to 40 (stride 80B: 16B-aligned rows,
// conflict-free LDSM), V rows padded to 72 (stride 144B: same properties).
#define SQ_H 0                       // Qh [128][40]
#define SQ_L (SQ_H + 128 * 40)       // Ql [128][40]
#define SK_H (SQ_L + 128 * 40)       // Kh [64][40]
#define SK_L (SK_H + 64 * 40)        // Kl [64][40]
#define SV   (SK_L + 64 * 40)        // V  [24][72]
#define SM_TOT (SV + 24 * 72)        // 17088 halves = 34176 B

__device__ __forceinline__ void mma16816(float c[4], const uint32_t a[4],
                                         uint32_t b0, uint32_t b1) {
    asm volatile(
        "mma.sync.aligned.m16n8k16.row.col.f32.f16.f16.f32 "
        "{%0,%1,%2,%3}, {%4,%5,%6,%7}, {%8,%9}, {%0,%1,%2,%3};"
        : "+f"(c[0]), "+f"(c[1]), "+f"(c[2]), "+f"(c[3])
        : "r"(a[0]), "r"(a[1]), "r"(a[2]), "r"(a[3]), "r"(b0), "r"(b1));
}

__device__ __forceinline__ void ldsm_x4(uint32_t& r0, uint32_t& r1,
                                        uint32_t& r2, uint32_t& r3, uint32_t addr) {
    asm volatile("ldmatrix.sync.aligned.m8n8.x4.shared.b16 {%0,%1,%2,%3}, [%4];"
                 : "=r"(r0), "=r"(r1), "=r"(r2), "=r"(r3) : "r"(addr));
}

__device__ __forceinline__ uint32_t packh2(float x, float y) {
    __half2 h = __floats2half2_rn(x, y);   // low <- x, high <- y
    return *(uint32_t*)&h;
}

__global__ __launch_bounds__(256, 2) void attn_mma_kernel(
        const float* __restrict__ qkv, const float* __restrict__ temp,
        float* __restrict__ att) {
    __shared__ __align__(16) __half sm[SM_TOT];
    const int tid = threadIdx.x;
    const int lane = tid & 31;
    const int warp = tid >> 5;
    const int g = lane >> 2;      // row group 0..7
    const int t = lane & 3;       // thread-in-group

    const int h = blockIdx.y;
    const int q0 = blockIdx.x * ATT_Q;
    const float scale = temp[h] * 1.4426950408889634f;  // temperature * log2(e)

    const float* qg = qkv + (h * HD) * NPIX;
    const float* kg = qkv + (C_DIM + h * HD) * NPIX;
    const float* vg = qkv + (2 * C_DIM + h * HD) * NPIX;

    // zero smem (padding columns must stay zero)
    for (int i = tid; i < SM_TOT; i += 256) sm[i] = __ushort_as_half(0);
    __syncthreads();

    // stage Q (scaled, hi/lo split), pairs along d, packed half2 stores
    #pragma unroll
    for (int i = 0; i < 6; i++) {
        int e = tid + i * 256;            // 128 q * 12 d-pairs = 1536
        int dp = e >> 7;                  // d-pair 0..11
        int qq = e & 127;
        float v0 = qg[(2 * dp) * NPIX + q0 + qq] * scale;
        float v1 = qg[(2 * dp + 1) * NPIX + q0 + qq] * scale;
        __half h0 = __float2half_rn(v0);
        __half h1 = __float2half_rn(v1);
        __half l0 = __float2half_rn(v0 - __half2float(h0));
        __half l1 = __float2half_rn(v1 - __half2float(h1));
        *(__half2*)&sm[SQ_H + qq * 40 + 2 * dp] = __halves2half2(h0, h1);
        *(__half2*)&sm[SQ_L + qq * 40 + 2 * dp] = __halves2half2(l0, l1);
    }
    __syncthreads();

    // load Q A-fragments (2 k-steps over d 0..31, cols 24..31 are zero pad)
    uint32_t aqh[2][4], aql[2][4];
    const int qr = warp * 16 + g;
    #pragma unroll
    for (int ks = 0; ks < 2; ks++) {
        int db = ks * 16 + t * 2;
        aqh[ks][0] = *(const uint32_t*)&sm[SQ_H + qr * 40 + db];
        aqh[ks][1] = *(const uint32_t*)&sm[SQ_H + (qr + 8) * 40 + db];
        aqh[ks][2] = *(const uint32_t*)&sm[SQ_H + qr * 40 + db + 8];
        aqh[ks][3] = *(const uint32_t*)&sm[SQ_H + (qr + 8) * 40 + db + 8];
        aql[ks][0] = *(const uint32_t*)&sm[SQ_L + qr * 40 + db];
        aql[ks][1] = *(const uint32_t*)&sm[SQ_L + (qr + 8) * 40 + db];
        aql[ks][2] = *(const uint32_t*)&sm[SQ_L + qr * 40 + db + 8];
        aql[ks][3] = *(const uint32_t*)&sm[SQ_L + (qr + 8) * 40 + db + 8];
    }

    // ldmatrix per-lane base addresses
    const uint32_t smb = (uint32_t)__cvta_generic_to_shared(sm);
    const int l7 = lane & 7;
    const int lc = (lane >> 3) * 8;
    const uint32_t kaddr_h = smb + SK_H * 2 + (l7 * 40 + lc) * 2;
    const uint32_t kaddr_l = smb + SK_L * 2 + (l7 * 40 + lc) * 2;
    const uint32_t vaddr   = smb + SV * 2 + (l7 * 72 + lc) * 2;

    float out[3][4];
    #pragma unroll
    for (int i = 0; i < 3; i++)
        #pragma unroll
        for (int j = 0; j < 4; j++) out[i][j] = 0.f;
    float m_a = -1e30f, m_b = -1e30f;   // row maxes (rows g, g+8) in log2 units
    float l_a = 0.f, l_b = 0.f;

    // prefetch chunk 0 (K d-pairs, V key-pairs) into registers
    float ka[3], kb[3];
    float2 vv[3];
    #pragma unroll
    for (int i = 0; i < 3; i++) {
        int e = tid + i * 256;            // 768 pair-slots
        int dp = e >> 6, j = e & 63;      // K: d-pair, key
        ka[i] = kg[(2 * dp) * NPIX + j];
        kb[i] = kg[(2 * dp + 1) * NPIX + j];
        int vd = e >> 5, jp = (e & 31) * 2;  // V: d, key-pair
        vv[i] = *(const float2*)&vg[vd * NPIX + jp];
    }

    for (int ch = 0; ch < NCHUNK; ch++) {
        __syncthreads();   // previous chunk's compute done
        // store staged regs -> smem (K hi/lo [key][40], V [d][72]) as half2
        #pragma unroll
        for (int i = 0; i < 3; i++) {
            int e = tid + i * 256;
            int dp = e >> 6, j = e & 63;
            __half h0 = __float2half_rn(ka[i]);
            __half h1 = __float2half_rn(kb[i]);
            __half l0 = __float2half_rn(ka[i] - __half2float(h0));
            __half l1 = __float2half_rn(kb[i] - __half2float(h1));
            *(__half2*)&sm[SK_H + j * 40 + 2 * dp] = __halves2half2(h0, h1);
            *(__half2*)&sm[SK_L + j * 40 + 2 * dp] = __halves2half2(l0, l1);
            int vd = e >> 5, jp = (e & 31) * 2;
            *(__half2*)&sm[SV + vd * 72 + jp] = __floats2half2_rn(vv[i].x, vv[i].y);
        }
        __syncthreads();
        // prefetch next chunk
        if (ch + 1 < NCHUNK) {
            int m0 = (ch + 1) * ATT_K;
            #pragma unroll
            for (int i = 0; i < 3; i++) {
                int e = tid + i * 256;
                int dp = e >> 6, j = e & 63;
                ka[i] = kg[(2 * dp) * NPIX + m0 + j];
                kb[i] = kg[(2 * dp + 1) * NPIX + m0 + j];
                int vd = e >> 5, jp = (e & 31) * 2;
                vv[i] = *(const float2*)&vg[vd * NPIX + m0 + jp];
            }
        }

        // ---- S = Q K^T (compensated), 8 n-tiles of 8 keys, LDSM fragments ----
        float s[8][4];
        #pragma unroll
        for (int nt = 0; nt < 8; nt++) {
            uint32_t h0, h1, h2, h3, L0, L1, L2, L3;
            ldsm_x4(h0, h1, h2, h3, kaddr_h + nt * 640);
            ldsm_x4(L0, L1, L2, L3, kaddr_l + nt * 640);
            s[nt][0] = s[nt][1] = s[nt][2] = s[nt][3] = 0.f;
            mma16816(s[nt], aqh[0], h0, h1);
            mma16816(s[nt], aqh[1], h2, h3);
            mma16816(s[nt], aql[0], h0, h1);
            mma16816(s[nt], aql[1], h2, h3);
            mma16816(s[nt], aqh[0], L0, L1);
            mma16816(s[nt], aqh[1], L2, L3);
        }

        // ---- online softmax (log2 domain) ----
        float ra = -1e30f, rb = -1e30f;
        #pragma unroll
        for (int nt = 0; nt < 8; nt++) {
            ra = fmaxf(ra, fmaxf(s[nt][0], s[nt][1]));
            rb = fmaxf(rb, fmaxf(s[nt][2], s[nt][3]));
        }
        ra = fmaxf(ra, __shfl_xor_sync(0xffffffffu, ra, 1));
        ra = fmaxf(ra, __shfl_xor_sync(0xffffffffu, ra, 2));
        rb = fmaxf(rb, __shfl_xor_sync(0xffffffffu, rb, 1));
        rb = fmaxf(rb, __shfl_xor_sync(0xffffffffu, rb, 2));
        float nma = fmaxf(m_a, ra);
        float nmb = fmaxf(m_b, rb);
        float ala = ex2f_fast(m_a - nma);
        float alb = ex2f_fast(m_b - nmb);
        m_a = nma; m_b = nmb;
        l_a *= ala; l_b *= alb;
        #pragma unroll
        for (int dnt = 0; dnt < 3; dnt++) {
            out[dnt][0] *= ala; out[dnt][1] *= ala;
            out[dnt][2] *= alb; out[dnt][3] *= alb;
        }
        float sa = 0.f, sb = 0.f;
        #pragma unroll
        for (int nt = 0; nt < 8; nt++) {
            s[nt][0] = ex2f_fast(s[nt][0] - m_a);
            s[nt][1] = ex2f_fast(s[nt][1] - m_a);
            s[nt][2] = ex2f_fast(s[nt][2] - m_b);
            s[nt][3] = ex2f_fast(s[nt][3] - m_b);
            sa += s[nt][0] + s[nt][1];
            sb += s[nt][2] + s[nt][3];
        }
        sa += __shfl_xor_sync(0xffffffffu, sa, 1);
        sa += __shfl_xor_sync(0xffffffffu, sa, 2);
        sb += __shfl_xor_sync(0xffffffffu, sb, 1);
        sb += __shfl_xor_sync(0xffffffffu, sb, 2);
        l_a += sa; l_b += sb;

        // ---- out += P V  (P: C-layout == A-layout trick), V via LDSM ----
        uint32_t pa[4][4];
        #pragma unroll
        for (int kv = 0; kv < 4; kv++) {
            pa[kv][0] = packh2(s[2 * kv][0],     s[2 * kv][1]);
            pa[kv][1] = packh2(s[2 * kv][2],     s[2 * kv][3]);
            pa[kv][2] = packh2(s[2 * kv + 1][0], s[2 * kv + 1][1]);
            pa[kv][3] = packh2(s[2 * kv + 1][2], s[2 * kv + 1][3]);
        }
        #pragma unroll
        for (int dnt = 0; dnt < 3; dnt++) {
            uint32_t v0, v1, v2, v3, v4, v5, v6, v7;
            ldsm_x4(v0, v1, v2, v3, vaddr + dnt * 1152);        // keys 0..31
            ldsm_x4(v4, v5, v6, v7, vaddr + dnt * 1152 + 64);   // keys 32..63
            mma16816(out[dnt], pa[0], v0, v1);
            mma16816(out[dnt], pa[1], v2, v3);
            mma16816(out[dnt], pa[2], v4, v5);
            mma16816(out[dnt], pa[3], v6, v7);
        }
    }

    // epilogue: normalize and store
    float inva = 1.0f / l_a;
    float invb = 1.0f / l_b;
    int qa = q0 + warp * 16 + g;
    int qb = qa + 8;
    #pragma unroll
    for (int dnt = 0; dnt < 3; dnt++) {
        int c0 = h * HD + dnt * 8 + t * 2;
        att[c0 * NPIX + qa]       = out[dnt][0] * inva;
        att[(c0 + 1) * NPIX + qa] = out[dnt][1] * inva;
        att[c0 * NPIX + qb]       = out[dnt][2] * invb;
        att[(c0 + 1) * NPIX + qb] = out[dnt][3] * invb;
    }
}

// ---------------- launch ----------------
extern "C" void kernel_launch(void* const* d_in, const int* in_sizes, int n_in,
                              void* d_out, int out_size) {
    const float* x      = (const float*)d_in[0];   // [192,4096]
    const float* gamma  = (const float*)d_in[1];   // [192]
    const float* beta   = (const float*)d_in[2];   // [192]
    const float* w_qkv  = (const float*)d_in[3];   // [576,192]
    const float* w_dw   = (const float*)d_in[4];   // [576,9]
    const float* b_dw   = (const float*)d_in[5];   // [576]
    const float* w_proj = (const float*)d_in[6];   // [192,192]
    const float* temper = (const float*)d_in[7];   // [8]
    float* out = (float*)d_out;

    float *xln, *qkvb, *qkvdw, *att;
    cudaGetSymbolAddress((void**)&xln,   g_xln);
    cudaGetSymbolAddress((void**)&qkvb,  g_qkv);
    cudaGetSymbolAddress((void**)&qkvdw, g_qkvdw);
    cudaGetSymbolAddress((void**)&att,   g_att);

    // 1. LayerNorm
    ln_kernel<<<NPIX / 256, 256>>>(x, gamma, beta, xln);

    // 2. qkv = w_qkv @ xln   [576,4096]
    {
        dim3 grid(NPIX / 64, QKV_CH / 64);
        gemm_kernel<<<grid, 256>>>(w_qkv, xln, nullptr, qkvb, QKV_CH, C_DIM, NPIX);
    }

    // 3. depthwise 3x3 + bias
    dwconv_kernel<<<(QKV_CH * NPIX) / 256, 256>>>(qkvb, w_dw, b_dw, qkvdw);

    // 4. tensor-core flash attention -> att [192,4096]
    {
        dim3 grid(NPIX / ATT_Q, HEADS);
        attn_mma_kernel<<<grid, 256>>>(qkvdw, temper, att);
    }

    // 5. out = w_proj @ att + x
    {
        dim3 grid(NPIX / 64, C_DIM / 64);
        gemm_kernel<<<grid, 256>>>(w_proj, att, x, out, C_DIM, C_DIM, NPIX);
    }
}